// round 7
// baseline (speedup 1.0000x reference)
#include <cuda_runtime.h>
#include <cuda_bf16.h>
#include <math.h>

#define Hh 2048
#define Bb 64
#define Ss 512
#define NCTA 128       // one CTA per 16 output columns
#define NT 16
#define NTHR 512       // 16 warps: 4 m-blocks x 4 k-quarters

// ---- static device scratch ----
// r stored as two bf16 planes (hi, lo-residual), PERMUTED fragment-native layout:
// ushort index = row*2048 + kbp*32 + tg*8 + parity*4 + e   (kbp = kb>>1, parity = kb&1)
// where element e of (kb, tg) is col {16kb+2tg, 16kb+2tg+1, 16kb+8+2tg, 16kb+8+2tg+1}[e]
__device__ unsigned short g_rh[2][Bb * Hh];
__device__ unsigned short g_rl[2][Bb * Hh];
__device__ float g_part[Ss][Bb][NCTA];        // per-CTA output partials
__device__ unsigned g_barcnt;
__device__ volatile unsigned g_bargen;

// ---------------------------------------------------------------------------
__device__ __forceinline__ void grid_sync() {
    __threadfence();
    __syncthreads();
    if (threadIdx.x == 0) {
        unsigned gen = g_bargen;
        if (atomicAdd(&g_barcnt, 1u) == NCTA - 1) {
            g_barcnt = 0;
            __threadfence();
            g_bargen = gen + 1;
        } else {
            while (g_bargen == gen) { }
        }
    }
    __syncthreads();
    __threadfence();
}

__device__ __forceinline__ unsigned pk2(__nv_bfloat16 a, __nv_bfloat16 b) {
    return (unsigned)__bfloat16_as_ushort(a) | ((unsigned)__bfloat16_as_ushort(b) << 16);
}

__device__ __forceinline__ void mma16816(float& d0, float& d1, float& d2, float& d3,
                                         unsigned a0, unsigned a1, unsigned a2, unsigned a3,
                                         unsigned b0, unsigned b1) {
    asm volatile(
        "mma.sync.aligned.m16n8k16.row.col.f32.bf16.bf16.f32 "
        "{%0,%1,%2,%3},{%4,%5,%6,%7},{%8,%9},{%0,%1,%2,%3};\n"
        : "+f"(d0), "+f"(d1), "+f"(d2), "+f"(d3)
        : "r"(a0), "r"(a1), "r"(a2), "r"(a3), "r"(b0), "r"(b1));
}

// ---------------------------------------------------------------------------
extern __shared__ uint4 smem_u4[];

__global__ void __launch_bounds__(NTHR, 1) rnn_mma_kernel(
    const float* __restrict__ x,          // [B,S,1]
    const float* __restrict__ noise,      // [B,S,H]
    const float* __restrict__ wi,         // [H]
    const float* __restrict__ wo,         // [H]
    const float* __restrict__ Av,         // [H]
    const float* __restrict__ rec_noise,  // [H,H]
    const float* __restrict__ owi,
    const float* __restrict__ owo,
    const float* __restrict__ omn,
    const float* __restrict__ h0,         // [H]
    float* __restrict__ out)              // [B,S,1]
{
    // SMEM: WfragH[128 kb][32 lanes] uint4 (hi), WfragL same (lo); red; fred 12KB
    uint4* WfragH = smem_u4;                 // 4096 uint4 (64 KB)
    uint4* WfragL = WfragH + 4096;           // 4096 uint4 (64 KB)
    float* red    = (float*)(WfragL + 4096); // 64 floats
    float* fred   = red + 64;                // 3072 floats (3 k-partial sets)

    const int tid  = threadIdx.x;
    const int cta  = blockIdx.x;
    const int col0 = cta * NT;
    const int wid  = tid >> 5;
    const int lane = tid & 31;
    const int g    = lane >> 2;
    const int tg   = lane & 3;
    const int mb   = wid & 3;          // m-block
    const int kq   = wid >> 2;         // k-quarter 0..3
    const int rowA = mb * 16 + g;
    const int rowB = rowA + 8;
    const int jA   = col0 + 2 * tg;         // tile0 cols jA, jA+1
    const int jB   = col0 + 8 + 2 * tg;     // tile1 cols jB, jB+1

    // ---- norms of wi, wo ----
    {
        float sa = 0.f, sb = 0.f;
        for (int i = tid; i < Hh; i += NTHR) {
            float u = wi[i]; sa = fmaf(u, u, sa);
            float v = wo[i]; sb = fmaf(v, v, sb);
        }
        for (int o = 16; o; o >>= 1) {
            sa += __shfl_down_sync(0xffffffffu, sa, o);
            sb += __shfl_down_sync(0xffffffffu, sb, o);
        }
        if (lane == 0) { red[wid] = sa; red[16 + wid] = sb; }
        __syncthreads();
        if (tid == 0) {
            float A2 = 0.f, B2 = 0.f;
            for (int i = 0; i < 16; i++) { A2 += red[i]; B2 += red[16 + i]; }
            red[32] = A2; red[33] = B2;
        }
        __syncthreads();
    }
    const float hf   = 2048.0f;
    const float invH = 1.0f / hf;
    const float cwi  = owi[0] * hf / red[32];
    const float cwo  = owo[0] * hf / red[33];
    const float cmn  = sqrtf(omn[0] * hf);
    __syncthreads();

    // ---- build W fragments (once): W[k][j] = n[k]*m[j]/H + rec_noise[k][j]
    {
        uint2* WH2 = (uint2*)WfragH;
        uint2* WL2 = (uint2*)WfragL;
        for (int s = tid; s < 8192; s += NTHR) {
            int kb = s >> 6;
            int nb = (s >> 5) & 1;
            int ln = s & 31;
            int gg = ln >> 2, tt = ln & 3;
            int k0 = kb * 16 + 2 * tt;
            int j  = col0 + nb * 8 + gg;
            float mj = cwo * wo[j] + cmn * Av[j];
            float w0, w1, w2, w3;
            {
                int k = k0;
                float nk = (cwi * wi[k] + cmn * Av[k]) * invH;
                w0 = fmaf(nk, mj, rec_noise[(size_t)k * Hh + j]);
                k = k0 + 1;
                nk = (cwi * wi[k] + cmn * Av[k]) * invH;
                w1 = fmaf(nk, mj, rec_noise[(size_t)k * Hh + j]);
                k = k0 + 8;
                nk = (cwi * wi[k] + cmn * Av[k]) * invH;
                w2 = fmaf(nk, mj, rec_noise[(size_t)k * Hh + j]);
                k = k0 + 9;
                nk = (cwi * wi[k] + cmn * Av[k]) * invH;
                w3 = fmaf(nk, mj, rec_noise[(size_t)k * Hh + j]);
            }
            __nv_bfloat16 h0b = __float2bfloat16(w0), h1b = __float2bfloat16(w1);
            __nv_bfloat16 h2b = __float2bfloat16(w2), h3b = __float2bfloat16(w3);
            uint2 hi; hi.x = pk2(h0b, h1b); hi.y = pk2(h2b, h3b);
            __nv_bfloat16 l0 = __float2bfloat16(w0 - __bfloat162float(h0b));
            __nv_bfloat16 l1 = __float2bfloat16(w1 - __bfloat162float(h1b));
            __nv_bfloat16 l2 = __float2bfloat16(w2 - __bfloat162float(h2b));
            __nv_bfloat16 l3 = __float2bfloat16(w3 - __bfloat162float(h3b));
            uint2 lo; lo.x = pk2(l0, l1); lo.y = pk2(l2, l3);
            int slot = kb * 64 + ln * 2 + nb;
            WH2[slot] = hi;
            WL2[slot] = lo;
        }
        __syncthreads();
    }

    // ---- register h (owned by kq==0 warps) ----
    float hA0 = h0[jA], hA1 = h0[jA + 1], hA2 = h0[jB], hA3 = h0[jB + 1];
    float hB0 = hA0,    hB1 = hA1,        hB2 = hA2,    hB3 = hA3;

    // writer uint2 index helper values
    const int wrIdxA = rowA * 512 + (cta >> 1) * 8 + tg * 2 + (cta & 1);
    const int wrIdxB = rowB * 512 + (cta >> 1) * 8 + tg * 2 + (cta & 1);

    if (kq == 0) {
        float rA0t = tanhf(hA0), rA1t = tanhf(hA1), rA2t = tanhf(hA2), rA3t = tanhf(hA3);
        uint2 vh, vl;
        vh.x = pk2(__float2bfloat16(rA0t), __float2bfloat16(rA1t));
        vh.y = pk2(__float2bfloat16(rA2t), __float2bfloat16(rA3t));
        vl.x = pk2(__float2bfloat16(rA0t - __bfloat162float(__float2bfloat16(rA0t))),
                   __float2bfloat16(rA1t - __bfloat162float(__float2bfloat16(rA1t))));
        vl.y = pk2(__float2bfloat16(rA2t - __bfloat162float(__float2bfloat16(rA2t))),
                   __float2bfloat16(rA3t - __bfloat162float(__float2bfloat16(rA3t))));
        ((uint2*)&g_rh[0][0])[wrIdxA] = vh;
        ((uint2*)&g_rl[0][0])[wrIdxA] = vl;
        ((uint2*)&g_rh[0][0])[wrIdxB] = vh;   // rowB starts identical (h0 same per col)
        ((uint2*)&g_rl[0][0])[wrIdxB] = vl;
    }
    grid_sync();

    const size_t nstride = (size_t)Ss * Hh;
    const int kbp0 = kq * 16;     // this warp's 16 kbp (= 32 kb) range

    // ---- main time loop ----
    for (int t = 0; t < Ss; t++) {
        const int cur = t & 1;
        const uint4* __restrict__ rinH = (const uint4*)&g_rh[cur][0];
        const uint4* __restrict__ rinL = (const uint4*)&g_rl[cur][0];

        // early loads (latency hidden under the MMA loop)
        float2 nA0, nA1, nB0, nB1;
        float xvA = 0.f, xvB = 0.f;
        if (kq == 0) {
            const float* npA = noise + (size_t)rowA * nstride + (size_t)t * Hh;
            const float* npB = npA + 8 * nstride;
            nA0 = *(const float2*)(npA + jA);
            nA1 = *(const float2*)(npA + jB);
            nB0 = *(const float2*)(npB + jA);
            nB1 = *(const float2*)(npB + jB);
            xvA = x[rowA * Ss + t];
            xvB = x[rowB * Ss + t];
        }

        float d00 = 0.f, d01 = 0.f, d02 = 0.f, d03 = 0.f;   // tile0 (cols jA)
        float d10 = 0.f, d11 = 0.f, d12 = 0.f, d13 = 0.f;   // tile1 (cols jB)

        // uint4 pointers: row*256 + kbp*4 + tg
        const uint4* pAh = rinH + (size_t)rowA * 256 + kbp0 * 4 + tg;
        const uint4* pAl = rinL + (size_t)rowA * 256 + kbp0 * 4 + tg;
        const uint4* pBh = rinH + (size_t)rowB * 256 + kbp0 * 4 + tg;
        const uint4* pBl = rinL + (size_t)rowB * 256 + kbp0 * 4 + tg;
        const uint4* wfh = WfragH + (size_t)(kbp0 * 2) * 32 + lane;
        const uint4* wfl = WfragL + (size_t)(kbp0 * 2) * 32 + lane;

        // depth-2 software prefetch
        uint4 fAh[2], fAl[2], fBh[2], fBl[2];
        fAh[0] = __ldcg(pAh);     fBh[0] = __ldcg(pBh);
        fAl[0] = __ldcg(pAl);     fBl[0] = __ldcg(pBl);
        fAh[1] = __ldcg(pAh + 4); fBh[1] = __ldcg(pBh + 4);
        fAl[1] = __ldcg(pAl + 4); fBl[1] = __ldcg(pBl + 4);

        #pragma unroll 4
        for (int i = 0; i < 16; i++) {
            uint4 aH = fAh[i & 1], bH = fBh[i & 1];
            uint4 aL = fAl[i & 1], bL = fBl[i & 1];
            if (i < 14) {
                fAh[i & 1] = __ldcg(pAh + (i + 2) * 4);
                fBh[i & 1] = __ldcg(pBh + (i + 2) * 4);
                fAl[i & 1] = __ldcg(pAl + (i + 2) * 4);
                fBl[i & 1] = __ldcg(pBl + (i + 2) * 4);
            }
            // kb even of this kbp
            {
                uint4 wh = wfh[(2 * i) * 32];
                uint4 wl = wfl[(2 * i) * 32];
                mma16816(d00, d01, d02, d03, aH.x, bH.x, aH.y, bH.y, wh.x, wh.y);
                mma16816(d10, d11, d12, d13, aH.x, bH.x, aH.y, bH.y, wh.z, wh.w);
                mma16816(d00, d01, d02, d03, aH.x, bH.x, aH.y, bH.y, wl.x, wl.y);
                mma16816(d10, d11, d12, d13, aH.x, bH.x, aH.y, bH.y, wl.z, wl.w);
                mma16816(d00, d01, d02, d03, aL.x, bL.x, aL.y, bL.y, wh.x, wh.y);
                mma16816(d10, d11, d12, d13, aL.x, bL.x, aL.y, bL.y, wh.z, wh.w);
            }
            // kb odd
            {
                uint4 wh = wfh[(2 * i + 1) * 32];
                uint4 wl = wfl[(2 * i + 1) * 32];
                mma16816(d00, d01, d02, d03, aH.z, bH.z, aH.w, bH.w, wh.x, wh.y);
                mma16816(d10, d11, d12, d13, aH.z, bH.z, aH.w, bH.w, wh.z, wh.w);
                mma16816(d00, d01, d02, d03, aH.z, bH.z, aH.w, bH.w, wl.x, wl.y);
                mma16816(d10, d11, d12, d13, aH.z, bH.z, aH.w, bH.w, wl.z, wl.w);
                mma16816(d00, d01, d02, d03, aL.z, bL.z, aL.w, bL.w, wh.x, wh.y);
                mma16816(d10, d11, d12, d13, aL.z, bL.z, aL.w, bL.w, wh.z, wh.w);
            }
        }

        // k-quarter partial exchange: kq 1..3 deposit, kq 0 merges
        if (kq > 0) {
            float* fp = fred + (kq - 1) * 1024 + mb * 256 + lane * 8;
            fp[0] = d00; fp[1] = d01; fp[2] = d02; fp[3] = d03;
            fp[4] = d10; fp[5] = d11; fp[6] = d12; fp[7] = d13;
        }
        __syncthreads();

        if (kq == 0) {
            #pragma unroll
            for (int q = 0; q < 3; q++) {
                const float* fp = fred + q * 1024 + mb * 256 + lane * 8;
                d00 += fp[0]; d01 += fp[1]; d02 += fp[2]; d03 += fp[3];
                d10 += fp[4]; d11 += fp[5]; d12 += fp[6]; d13 += fp[7];
            }

            float wiA0 = __ldg(wi + jA), wiA1 = __ldg(wi + jA + 1);
            float wiB0 = __ldg(wi + jB), wiB1 = __ldg(wi + jB + 1);

            hA0 = 0.8f * hA0 + 0.05f * nA0.x + 0.2f * (d00 + xvA * wiA0);
            hA1 = 0.8f * hA1 + 0.05f * nA0.y + 0.2f * (d01 + xvA * wiA1);
            hB0 = 0.8f * hB0 + 0.05f * nB0.x + 0.2f * (d02 + xvB * wiA0);
            hB1 = 0.8f * hB1 + 0.05f * nB0.y + 0.2f * (d03 + xvB * wiA1);
            hA2 = 0.8f * hA2 + 0.05f * nA1.x + 0.2f * (d10 + xvA * wiB0);
            hA3 = 0.8f * hA3 + 0.05f * nA1.y + 0.2f * (d11 + xvA * wiB1);
            hB2 = 0.8f * hB2 + 0.05f * nB1.x + 0.2f * (d12 + xvB * wiB0);
            hB3 = 0.8f * hB3 + 0.05f * nB1.y + 0.2f * (d13 + xvB * wiB1);

            float rA0 = tanhf(hA0), rA1 = tanhf(hA1), rA2 = tanhf(hA2), rA3 = tanhf(hA3);
            float rB0 = tanhf(hB0), rB1 = tanhf(hB1), rB2 = tanhf(hB2), rB3 = tanhf(hB3);

            const int nxt = cur ^ 1;
            uint2* routh = (uint2*)&g_rh[nxt][0];
            uint2* routl = (uint2*)&g_rl[nxt][0];

            __nv_bfloat16 hA0b = __float2bfloat16(rA0), hA1b = __float2bfloat16(rA1);
            __nv_bfloat16 hA2b = __float2bfloat16(rA2), hA3b = __float2bfloat16(rA3);
            __nv_bfloat16 hB0b = __float2bfloat16(rB0), hB1b = __float2bfloat16(rB1);
            __nv_bfloat16 hB2b = __float2bfloat16(rB2), hB3b = __float2bfloat16(rB3);

            uint2 v;
            v.x = pk2(hA0b, hA1b); v.y = pk2(hA2b, hA3b);
            __stcg(routh + wrIdxA, v);
            v.x = pk2(__float2bfloat16(rA0 - __bfloat162float(hA0b)),
                      __float2bfloat16(rA1 - __bfloat162float(hA1b)));
            v.y = pk2(__float2bfloat16(rA2 - __bfloat162float(hA2b)),
                      __float2bfloat16(rA3 - __bfloat162float(hA3b)));
            __stcg(routl + wrIdxA, v);
            v.x = pk2(hB0b, hB1b); v.y = pk2(hB2b, hB3b);
            __stcg(routh + wrIdxB, v);
            v.x = pk2(__float2bfloat16(rB0 - __bfloat162float(hB0b)),
                      __float2bfloat16(rB1 - __bfloat162float(hB1b)));
            v.y = pk2(__float2bfloat16(rB2 - __bfloat162float(hB2b)),
                      __float2bfloat16(rB3 - __bfloat162float(hB3b)));
            __stcg(routl + wrIdxB, v);

            // out partial over this warp's 16 cols
            float woA0 = __ldg(wo + jA), woA1 = __ldg(wo + jA + 1);
            float woB0 = __ldg(wo + jB), woB1 = __ldg(wo + jB + 1);
            float pAo = fmaf(rA0, woA0, fmaf(rA1, woA1, fmaf(rA2, woB0, rA3 * woB1)));
            float pBo = fmaf(rB0, woA0, fmaf(rB1, woA1, fmaf(rB2, woB0, rB3 * woB1)));
            #pragma unroll
            for (int o = 2; o; o >>= 1) {
                pAo += __shfl_down_sync(0xffffffffu, pAo, o, 4);
                pBo += __shfl_down_sync(0xffffffffu, pBo, o, 4);
            }
            if (tg == 0) {
                g_part[t][rowA][cta] = pAo;
                g_part[t][rowB][cta] = pBo;
            }
        }
        grid_sync();
    }

    // ---- tail: reduce partials -> out ----
    if (tid < 256) {
        int pair = cta * 256 + tid;     // 0..32767 = Ss*Bb
        int tt = pair >> 6;
        int b  = pair & 63;
        const float* pp = &g_part[tt][b][0];
        float s = 0.f;
        #pragma unroll
        for (int c = 0; c < NCTA; c += 4) {
            float4 v = *(const float4*)(pp + c);
            s += (v.x + v.y) + (v.z + v.w);
        }
        out[b * Ss + tt] = s * (1.0f / 2048.0f);
    }
}

// ---------------------------------------------------------------------------
extern "C" void kernel_launch(void* const* d_in, const int* in_sizes, int n_in,
                              void* d_out, int out_size) {
    const float* x         = (const float*)d_in[0];
    const float* noise     = (const float*)d_in[1];
    const float* wi        = (const float*)d_in[2];
    const float* wo        = (const float*)d_in[3];
    const float* A         = (const float*)d_in[4];
    const float* rec_noise = (const float*)d_in[5];
    const float* owi       = (const float*)d_in[6];
    const float* owo       = (const float*)d_in[7];
    const float* omn       = (const float*)d_in[8];
    const float* h0        = (const float*)d_in[9];
    float* out = (float*)d_out;

    const int smem_bytes = 131072 + 64 * 4 + 3072 * 4;   // WfragH/L + red + fred
    static int attr_done = 0;
    if (!attr_done) {
        cudaFuncSetAttribute(rnn_mma_kernel,
                             cudaFuncAttributeMaxDynamicSharedMemorySize, smem_bytes);
        attr_done = 1;
    }

    rnn_mma_kernel<<<NCTA, NTHR, smem_bytes>>>(
        x, noise, wi, wo, A, rec_noise, owi, owo, omn, h0, out);
}

// round 8
// speedup vs baseline: 1.4795x; 1.4795x over previous
#include <cuda_runtime.h>
#include <cuda_bf16.h>
#include <math.h>

#define Hh 2048
#define Bb 64
#define Ss 512
#define NCTA 128       // one CTA per 16 output columns
#define NT 16
#define NTHR 256       // 8 warps: 4 m-blocks x 2 k-halves

// ---- static device scratch ----
// r stored as two bf16 planes (hi, lo-residual), fragment-native permuted layout:
// per row (2048 ushort = 256 uint4): uint4 index = kbp*4 + tg  (kbp = kb>>1)
// holding, for kb=2*kbp (+parity), thread tg's fragment elements
// {16kb+2tg, 16kb+2tg+1, 16kb+8+2tg, 16kb+8+2tg+1} (4 per kb; 8 per uint4)
__device__ unsigned short g_rh[2][Bb * Hh];
__device__ unsigned short g_rl[2][Bb * Hh];
__device__ float g_part[Ss][Bb][NCTA];        // per-CTA output partials
__device__ unsigned g_barcnt;
__device__ volatile unsigned g_bargen;

// ---------------------------------------------------------------------------
__device__ __forceinline__ void grid_sync() {
    __threadfence();
    __syncthreads();
    if (threadIdx.x == 0) {
        unsigned gen = g_bargen;
        if (atomicAdd(&g_barcnt, 1u) == NCTA - 1) {
            g_barcnt = 0;
            __threadfence();
            g_bargen = gen + 1;
        } else {
            while (g_bargen == gen) { }
        }
    }
    __syncthreads();
    __threadfence();
}

__device__ __forceinline__ unsigned pk2(__nv_bfloat16 a, __nv_bfloat16 b) {
    return (unsigned)__bfloat16_as_ushort(a) | ((unsigned)__bfloat16_as_ushort(b) << 16);
}

__device__ __forceinline__ void mma16816(float& d0, float& d1, float& d2, float& d3,
                                         unsigned a0, unsigned a1, unsigned a2, unsigned a3,
                                         unsigned b0, unsigned b1) {
    asm volatile(
        "mma.sync.aligned.m16n8k16.row.col.f32.bf16.bf16.f32 "
        "{%0,%1,%2,%3},{%4,%5,%6,%7},{%8,%9},{%0,%1,%2,%3};\n"
        : "+f"(d0), "+f"(d1), "+f"(d2), "+f"(d3)
        : "r"(a0), "r"(a1), "r"(a2), "r"(a3), "r"(b0), "r"(b1));
}

// ---------------------------------------------------------------------------
extern __shared__ uint4 smem_u4[];

__global__ void __launch_bounds__(NTHR, 1) rnn_mma_kernel(
    const float* __restrict__ x,          // [B,S,1]
    const float* __restrict__ noise,      // [B,S,H]
    const float* __restrict__ wi,         // [H]
    const float* __restrict__ wo,         // [H]
    const float* __restrict__ Av,         // [H]
    const float* __restrict__ rec_noise,  // [H,H]
    const float* __restrict__ owi,
    const float* __restrict__ owo,
    const float* __restrict__ omn,
    const float* __restrict__ h0,         // [H]
    float* __restrict__ out)              // [B,S,1]
{
    // SMEM: WfragH[128 kb][32 lanes] uint4 (hi), WfragL same (lo); red; fred 4KB
    uint4* WfragH = smem_u4;                 // 4096 uint4 (64 KB)
    uint4* WfragL = WfragH + 4096;           // 4096 uint4 (64 KB)
    float* red    = (float*)(WfragL + 4096); // 64 floats
    float* fred   = red + 64;                // 1024 floats

    const int tid  = threadIdx.x;
    const int cta  = blockIdx.x;
    const int col0 = cta * NT;
    const int wid  = tid >> 5;
    const int lane = tid & 31;
    const int g    = lane >> 2;
    const int tg   = lane & 3;
    const int mb   = wid & 3;          // m-block
    const bool khigh = wid >= 4;       // k-half
    const int rowA = mb * 16 + g;
    const int rowB = rowA + 8;
    const int jA   = col0 + 2 * tg;         // tile0 cols jA, jA+1
    const int jB   = col0 + 8 + 2 * tg;     // tile1 cols jB, jB+1

    // ---- norms of wi, wo ----
    {
        float sa = 0.f, sb = 0.f;
        for (int i = tid; i < Hh; i += NTHR) {
            float u = wi[i]; sa = fmaf(u, u, sa);
            float v = wo[i]; sb = fmaf(v, v, sb);
        }
        for (int o = 16; o; o >>= 1) {
            sa += __shfl_down_sync(0xffffffffu, sa, o);
            sb += __shfl_down_sync(0xffffffffu, sb, o);
        }
        if (lane == 0) { red[wid] = sa; red[8 + wid] = sb; }
        __syncthreads();
        if (tid == 0) {
            float A2 = 0.f, B2 = 0.f;
            for (int i = 0; i < 8; i++) { A2 += red[i]; B2 += red[8 + i]; }
            red[16] = A2; red[17] = B2;
        }
        __syncthreads();
    }
    const float hf   = 2048.0f;
    const float invH = 1.0f / hf;
    const float cwi  = owi[0] * hf / red[16];
    const float cwo  = owo[0] * hf / red[17];
    const float cmn  = sqrtf(omn[0] * hf);
    __syncthreads();

    // ---- build W fragments (once): W[k][j] = n[k]*m[j]/H + rec_noise[k][j]
    {
        uint2* WH2 = (uint2*)WfragH;
        uint2* WL2 = (uint2*)WfragL;
        for (int s = tid; s < 8192; s += NTHR) {
            int kb = s >> 6;
            int nb = (s >> 5) & 1;
            int ln = s & 31;
            int gg = ln >> 2, tt = ln & 3;
            int k0 = kb * 16 + 2 * tt;
            int j  = col0 + nb * 8 + gg;
            float mj = cwo * wo[j] + cmn * Av[j];
            float w0, w1, w2, w3;
            {
                int k = k0;
                float nk = (cwi * wi[k] + cmn * Av[k]) * invH;
                w0 = fmaf(nk, mj, rec_noise[(size_t)k * Hh + j]);
                k = k0 + 1;
                nk = (cwi * wi[k] + cmn * Av[k]) * invH;
                w1 = fmaf(nk, mj, rec_noise[(size_t)k * Hh + j]);
                k = k0 + 8;
                nk = (cwi * wi[k] + cmn * Av[k]) * invH;
                w2 = fmaf(nk, mj, rec_noise[(size_t)k * Hh + j]);
                k = k0 + 9;
                nk = (cwi * wi[k] + cmn * Av[k]) * invH;
                w3 = fmaf(nk, mj, rec_noise[(size_t)k * Hh + j]);
            }
            __nv_bfloat16 h0b = __float2bfloat16(w0), h1b = __float2bfloat16(w1);
            __nv_bfloat16 h2b = __float2bfloat16(w2), h3b = __float2bfloat16(w3);
            uint2 hi; hi.x = pk2(h0b, h1b); hi.y = pk2(h2b, h3b);
            __nv_bfloat16 l0 = __float2bfloat16(w0 - __bfloat162float(h0b));
            __nv_bfloat16 l1 = __float2bfloat16(w1 - __bfloat162float(h1b));
            __nv_bfloat16 l2 = __float2bfloat16(w2 - __bfloat162float(h2b));
            __nv_bfloat16 l3 = __float2bfloat16(w3 - __bfloat162float(h3b));
            uint2 lo; lo.x = pk2(l0, l1); lo.y = pk2(l2, l3);
            int slot = kb * 64 + ln * 2 + nb;
            WH2[slot] = hi;
            WL2[slot] = lo;
        }
        __syncthreads();
    }

    // ---- per-thread constants + register h (owned by klow warps) ----
    const float wiA0 = wi[jA], wiA1 = wi[jA + 1];
    const float wiB0 = wi[jB], wiB1 = wi[jB + 1];
    const float woA0 = wo[jA], woA1 = wo[jA + 1];
    const float woB0 = wo[jB], woB1 = wo[jB + 1];

    float hA0 = h0[jA], hA1 = h0[jA + 1], hA2 = h0[jB], hA3 = h0[jB + 1];
    float hB0 = hA0,    hB1 = hA1,        hB2 = hA2,    hB3 = hA3;

    // writer uint2 indices (uint2 = 4 elements; kb block 'cta' covers our 16 cols)
    const int wrIdxA = rowA * 512 + (cta >> 1) * 8 + tg * 2 + (cta & 1);
    const int wrIdxB = rowB * 512 + (cta >> 1) * 8 + tg * 2 + (cta & 1);

    if (!khigh) {
        float rA0t = tanhf(hA0), rA1t = tanhf(hA1), rA2t = tanhf(hA2), rA3t = tanhf(hA3);
        __nv_bfloat16 b0 = __float2bfloat16(rA0t), b1 = __float2bfloat16(rA1t);
        __nv_bfloat16 b2 = __float2bfloat16(rA2t), b3 = __float2bfloat16(rA3t);
        uint2 vh, vl;
        vh.x = pk2(b0, b1); vh.y = pk2(b2, b3);
        vl.x = pk2(__float2bfloat16(rA0t - __bfloat162float(b0)),
                   __float2bfloat16(rA1t - __bfloat162float(b1)));
        vl.y = pk2(__float2bfloat16(rA2t - __bfloat162float(b2)),
                   __float2bfloat16(rA3t - __bfloat162float(b3)));
        ((uint2*)&g_rh[0][0])[wrIdxA] = vh;
        ((uint2*)&g_rl[0][0])[wrIdxA] = vl;
        ((uint2*)&g_rh[0][0])[wrIdxB] = vh;   // rowB starts identical (h0 per col)
        ((uint2*)&g_rl[0][0])[wrIdxB] = vl;
    }
    grid_sync();

    const size_t nstride = (size_t)Ss * Hh;
    const int kbp0 = khigh ? 32 : 0;      // 32 kbp (=64 kb) per k-half

    // ---- main time loop ----
    for (int t = 0; t < Ss; t++) {
        const int cur = t & 1;
        const uint4* __restrict__ rinH = (const uint4*)&g_rh[cur][0];
        const uint4* __restrict__ rinL = (const uint4*)&g_rl[cur][0];

        // early loads (latency hidden under the MMA loop)
        float2 nA0, nA1, nB0, nB1;
        float xvA = 0.f, xvB = 0.f;
        if (!khigh) {
            const float* npA = noise + (size_t)rowA * nstride + (size_t)t * Hh;
            const float* npB = npA + 8 * nstride;
            nA0 = *(const float2*)(npA + jA);
            nA1 = *(const float2*)(npA + jB);
            nB0 = *(const float2*)(npB + jA);
            nB1 = *(const float2*)(npB + jB);
            xvA = x[rowA * Ss + t];
            xvB = x[rowB * Ss + t];
        }

        float d00 = 0.f, d01 = 0.f, d02 = 0.f, d03 = 0.f;   // tile0 (cols jA)
        float d10 = 0.f, d11 = 0.f, d12 = 0.f, d13 = 0.f;   // tile1 (cols jB)

        const uint4* pAh = rinH + (size_t)rowA * 256 + kbp0 * 4 + tg;
        const uint4* pAl = rinL + (size_t)rowA * 256 + kbp0 * 4 + tg;
        const uint4* pBh = rinH + (size_t)rowB * 256 + kbp0 * 4 + tg;
        const uint4* pBl = rinL + (size_t)rowB * 256 + kbp0 * 4 + tg;
        const uint4* wfh = WfragH + (size_t)(kbp0 * 2) * 32 + lane;
        const uint4* wfl = WfragL + (size_t)(kbp0 * 2) * 32 + lane;

        // depth-2 software prefetch
        uint4 fAh[2], fAl[2], fBh[2], fBl[2];
        fAh[0] = __ldcg(pAh);     fBh[0] = __ldcg(pBh);
        fAl[0] = __ldcg(pAl);     fBl[0] = __ldcg(pBl);
        fAh[1] = __ldcg(pAh + 4); fBh[1] = __ldcg(pBh + 4);
        fAl[1] = __ldcg(pAl + 4); fBl[1] = __ldcg(pBl + 4);

        #pragma unroll 4
        for (int i = 0; i < 32; i++) {
            uint4 aH = fAh[i & 1], bH = fBh[i & 1];
            uint4 aL = fAl[i & 1], bL = fBl[i & 1];
            if (i < 30) {
                fAh[i & 1] = __ldcg(pAh + (i + 2) * 4);
                fBh[i & 1] = __ldcg(pBh + (i + 2) * 4);
                fAl[i & 1] = __ldcg(pAl + (i + 2) * 4);
                fBl[i & 1] = __ldcg(pBl + (i + 2) * 4);
            }
            // kb even of this kbp
            {
                uint4 wh = wfh[(2 * i) * 32];
                uint4 wl = wfl[(2 * i) * 32];
                mma16816(d00, d01, d02, d03, aH.x, bH.x, aH.y, bH.y, wh.x, wh.y);
                mma16816(d10, d11, d12, d13, aH.x, bH.x, aH.y, bH.y, wh.z, wh.w);
                mma16816(d00, d01, d02, d03, aH.x, bH.x, aH.y, bH.y, wl.x, wl.y);
                mma16816(d10, d11, d12, d13, aH.x, bH.x, aH.y, bH.y, wl.z, wl.w);
                mma16816(d00, d01, d02, d03, aL.x, bL.x, aL.y, bL.y, wh.x, wh.y);
                mma16816(d10, d11, d12, d13, aL.x, bL.x, aL.y, bL.y, wh.z, wh.w);
            }
            // kb odd
            {
                uint4 wh = wfh[(2 * i + 1) * 32];
                uint4 wl = wfl[(2 * i + 1) * 32];
                mma16816(d00, d01, d02, d03, aH.z, bH.z, aH.w, bH.w, wh.x, wh.y);
                mma16816(d10, d11, d12, d13, aH.z, bH.z, aH.w, bH.w, wh.z, wh.w);
                mma16816(d00, d01, d02, d03, aH.z, bH.z, aH.w, bH.w, wl.x, wl.y);
                mma16816(d10, d11, d12, d13, aH.z, bH.z, aH.w, bH.w, wl.z, wl.w);
                mma16816(d00, d01, d02, d03, aL.z, bL.z, aL.w, bL.w, wh.x, wh.y);
                mma16816(d10, d11, d12, d13, aL.z, bL.z, aL.w, bL.w, wh.z, wh.w);
            }
        }

        // k-half partial exchange
        if (khigh) {
            float* fp = fred + (wid - 4) * 256 + lane * 8;
            fp[0] = d00; fp[1] = d01; fp[2] = d02; fp[3] = d03;
            fp[4] = d10; fp[5] = d11; fp[6] = d12; fp[7] = d13;
        }
        __syncthreads();

        if (!khigh) {
            const float* fp = fred + wid * 256 + lane * 8;
            d00 += fp[0]; d01 += fp[1]; d02 += fp[2]; d03 += fp[3];
            d10 += fp[4]; d11 += fp[5]; d12 += fp[6]; d13 += fp[7];

            hA0 = 0.8f * hA0 + 0.05f * nA0.x + 0.2f * (d00 + xvA * wiA0);
            hA1 = 0.8f * hA1 + 0.05f * nA0.y + 0.2f * (d01 + xvA * wiA1);
            hB0 = 0.8f * hB0 + 0.05f * nB0.x + 0.2f * (d02 + xvB * wiA0);
            hB1 = 0.8f * hB1 + 0.05f * nB0.y + 0.2f * (d03 + xvB * wiA1);
            hA2 = 0.8f * hA2 + 0.05f * nA1.x + 0.2f * (d10 + xvA * wiB0);
            hA3 = 0.8f * hA3 + 0.05f * nA1.y + 0.2f * (d11 + xvA * wiB1);
            hB2 = 0.8f * hB2 + 0.05f * nB1.x + 0.2f * (d12 + xvB * wiB0);
            hB3 = 0.8f * hB3 + 0.05f * nB1.y + 0.2f * (d13 + xvB * wiB1);

            float rA0 = tanhf(hA0), rA1 = tanhf(hA1), rA2 = tanhf(hA2), rA3 = tanhf(hA3);
            float rB0 = tanhf(hB0), rB1 = tanhf(hB1), rB2 = tanhf(hB2), rB3 = tanhf(hB3);

            const int nxt = cur ^ 1;
            uint2* routh = (uint2*)&g_rh[nxt][0];
            uint2* routl = (uint2*)&g_rl[nxt][0];

            __nv_bfloat16 hA0b = __float2bfloat16(rA0), hA1b = __float2bfloat16(rA1);
            __nv_bfloat16 hA2b = __float2bfloat16(rA2), hA3b = __float2bfloat16(rA3);
            __nv_bfloat16 hB0b = __float2bfloat16(rB0), hB1b = __float2bfloat16(rB1);
            __nv_bfloat16 hB2b = __float2bfloat16(rB2), hB3b = __float2bfloat16(rB3);

            uint2 v;
            v.x = pk2(hA0b, hA1b); v.y = pk2(hA2b, hA3b);
            __stcg(routh + wrIdxA, v);
            v.x = pk2(__float2bfloat16(rA0 - __bfloat162float(hA0b)),
                      __float2bfloat16(rA1 - __bfloat162float(hA1b)));
            v.y = pk2(__float2bfloat16(rA2 - __bfloat162float(hA2b)),
                      __float2bfloat16(rA3 - __bfloat162float(hA3b)));
            __stcg(routl + wrIdxA, v);
            v.x = pk2(hB0b, hB1b); v.y = pk2(hB2b, hB3b);
            __stcg(routh + wrIdxB, v);
            v.x = pk2(__float2bfloat16(rB0 - __bfloat162float(hB0b)),
                      __float2bfloat16(rB1 - __bfloat162float(hB1b)));
            v.y = pk2(__float2bfloat16(rB2 - __bfloat162float(hB2b)),
                      __float2bfloat16(rB3 - __bfloat162float(hB3b)));
            __stcg(routl + wrIdxB, v);

            // out partial over this warp's 16 cols
            float pAo = fmaf(rA0, woA0, fmaf(rA1, woA1, fmaf(rA2, woB0, rA3 * woB1)));
            float pBo = fmaf(rB0, woA0, fmaf(rB1, woA1, fmaf(rB2, woB0, rB3 * woB1)));
            #pragma unroll
            for (int o = 2; o; o >>= 1) {
                pAo += __shfl_down_sync(0xffffffffu, pAo, o, 4);
                pBo += __shfl_down_sync(0xffffffffu, pBo, o, 4);
            }
            if (tg == 0) {
                g_part[t][rowA][cta] = pAo;
                g_part[t][rowB][cta] = pBo;
            }
        }
        grid_sync();
    }

    // ---- tail: reduce partials -> out ----
    {
        int pair = cta * 256 + tid;     // 0..32767 = Ss*Bb
        int tt = pair >> 6;
        int b  = pair & 63;
        const float* pp = &g_part[tt][b][0];
        float s = 0.f;
        #pragma unroll
        for (int c = 0; c < NCTA; c += 4) {
            float4 v = *(const float4*)(pp + c);
            s += (v.x + v.y) + (v.z + v.w);
        }
        out[b * Ss + tt] = s * (1.0f / 2048.0f);
    }
}

// ---------------------------------------------------------------------------
extern "C" void kernel_launch(void* const* d_in, const int* in_sizes, int n_in,
                              void* d_out, int out_size) {
    const float* x         = (const float*)d_in[0];
    const float* noise     = (const float*)d_in[1];
    const float* wi        = (const float*)d_in[2];
    const float* wo        = (const float*)d_in[3];
    const float* A         = (const float*)d_in[4];
    const float* rec_noise = (const float*)d_in[5];
    const float* owi       = (const float*)d_in[6];
    const float* owo       = (const float*)d_in[7];
    const float* omn       = (const float*)d_in[8];
    const float* h0        = (const float*)d_in[9];
    float* out = (float*)d_out;

    const int smem_bytes = 131072 + 64 * 4 + 1024 * 4;   // WfragH/L + red + fred
    static int attr_done = 0;
    if (!attr_done) {
        cudaFuncSetAttribute(rnn_mma_kernel,
                             cudaFuncAttributeMaxDynamicSharedMemorySize, smem_bytes);
        attr_done = 1;
    }

    rnn_mma_kernel<<<NCTA, NTHR, smem_bytes>>>(
        x, noise, wi, wo, A, rec_noise, owi, owo, omn, h0, out);
}